// round 1
// baseline (speedup 1.0000x reference)
#include <cuda_runtime.h>
#include <math.h>

#define T_STEPS 8
#define NN      10000
#define EE      200000
#define FIN     32
#define HID     128
#define OUTD    64
#define G4      256            // 4*OUT
#define MROWS   (T_STEPS*NN)   // 80000
#define EPSBN   1e-5f

// ---------------- scratch (device globals; no allocations allowed) ----------
static __device__ float g_hw [MROWS*HID];   // GEMM output (pre-aggregation)
static __device__ float g_h  [MROWS*HID];   // GCN layer output
static __device__ float g_pre[MROWS*G4];    // LSTM input projections
static __device__ float g_ysA[MROWS*OUTD];
static __device__ float g_ysB[MROWS*OUTD];
static __device__ float g_dis[NN];
static __device__ int   g_cnt[NN];
static __device__ int   g_rowptr[NN+1];
static __device__ int   g_cursor[NN];
static __device__ int   g_csr_src[EE];
static __device__ float g_csr_coef[EE];
static __device__ float g_wih0t[HID*G4];    // transposed w_ih_0: [128][256]
static __device__ float g_wih1t[OUTD*G4];   // [64][256]
static __device__ float g_wih2t[OUTD*G4];
static __device__ float g_biasc[3*G4];      // b_ih + b_hh per layer

// ---------------- graph setup kernels ----------------
__global__ void k_zero_cnt() {
    int i = blockIdx.x * blockDim.x + threadIdx.x;
    if (i < NN) g_cnt[i] = 0;
}

__global__ void k_hist(const int* __restrict__ dst) {
    int e = blockIdx.x * blockDim.x + threadIdx.x;
    if (e < EE) atomicAdd(&g_cnt[dst[e]], 1);
}

__global__ void k_dis() {
    int i = blockIdx.x * blockDim.x + threadIdx.x;
    if (i < NN) g_dis[i] = rsqrtf((float)g_cnt[i] + 1.0f);
}

__global__ void k_scan() {
    const int TPB = 1024, PER = 10;   // covers 10240 >= NN+1
    __shared__ int sh[TPB];
    int tid  = threadIdx.x;
    int base = tid * PER;
    int loc[PER];
    int s = 0;
#pragma unroll
    for (int i = 0; i < PER; i++) {
        int idx = base + i;
        int v = (idx < NN) ? g_cnt[idx] : 0;
        loc[i] = s; s += v;
    }
    sh[tid] = s; __syncthreads();
    for (int off = 1; off < TPB; off <<= 1) {
        int v = (tid >= off) ? sh[tid - off] : 0;
        __syncthreads();
        sh[tid] += v;
        __syncthreads();
    }
    int excl = (tid == 0) ? 0 : sh[tid - 1];
#pragma unroll
    for (int i = 0; i < PER; i++) {
        int idx = base + i;
        if (idx <= NN) g_rowptr[idx] = excl + loc[i];
    }
}

__global__ void k_copy_cursor() {
    int i = blockIdx.x * blockDim.x + threadIdx.x;
    if (i < NN) g_cursor[i] = g_rowptr[i];
}

__global__ void k_fill(const int* __restrict__ src, const int* __restrict__ dst) {
    int e = blockIdx.x * blockDim.x + threadIdx.x;
    if (e < EE) {
        int s = src[e], d = dst[e];
        int p = atomicAdd(&g_cursor[d], 1);
        g_csr_src[p]  = s;
        g_csr_coef[p] = g_dis[s] * g_dis[d];
    }
}

__global__ void k_transpose(const float* __restrict__ W, float* __restrict__ Wt, int K) {
    // W: [256, K] row-major -> Wt: [K, 256]
    int idx = blockIdx.x * blockDim.x + threadIdx.x;
    if (idx < G4 * K) {
        int j = idx / K, k = idx % K;
        Wt[k * G4 + j] = W[idx];
    }
}

__global__ void k_bias_sum(const float* __restrict__ a, const float* __restrict__ b,
                           float* __restrict__ o) {
    int i = threadIdx.x;
    o[i] = a[i] + b[i];
}

// ---------------- GEMM: C[M,Nout] = A[M,K] @ B[K,Nout] (+ bias) -------------
// block: 256 threads, tile 64 x 128, K in chunks of 32. M%64==0, Nout%128==0, K%32==0.
__global__ void k_gemm(const float* __restrict__ A, const float* __restrict__ B,
                       const float* __restrict__ bias, float* __restrict__ C,
                       int M, int K, int Nout) {
    __shared__ float As[32][68];
    __shared__ float Bs[32][128];
    int tid = threadIdx.x;
    int tx = tid & 15, ty = tid >> 4;
    int mBase = blockIdx.x * 64;
    int jBase = blockIdx.y * 128;

    float acc[4][8];
#pragma unroll
    for (int i = 0; i < 4; i++)
#pragma unroll
        for (int j = 0; j < 8; j++) acc[i][j] = 0.0f;

    for (int kc = 0; kc < K; kc += 32) {
        // A tile 64x32 (transposed into As[k][m])
#pragma unroll
        for (int s = 0; s < 2; s++) {
            int slot = tid + s * 256;          // 0..511 float4 slots
            int row = slot >> 3, kv = slot & 7;
            float4 a4 = *(const float4*)(A + (size_t)(mBase + row) * K + kc + kv * 4);
            As[kv * 4 + 0][row] = a4.x;
            As[kv * 4 + 1][row] = a4.y;
            As[kv * 4 + 2][row] = a4.z;
            As[kv * 4 + 3][row] = a4.w;
        }
        // B tile 32x128
#pragma unroll
        for (int s = 0; s < 4; s++) {
            int slot = tid + s * 256;          // 0..1023 float4 slots
            int row = slot >> 5, jv = slot & 31;
            float4 b4 = *(const float4*)(B + (size_t)(kc + row) * Nout + jBase + jv * 4);
            *(float4*)&Bs[row][jv * 4] = b4;
        }
        __syncthreads();
#pragma unroll
        for (int kk = 0; kk < 32; kk++) {
            float a[4];
#pragma unroll
            for (int i = 0; i < 4; i++) a[i] = As[kk][ty * 4 + i];
            float4 b0 = *(float4*)&Bs[kk][tx * 8];
            float4 b1 = *(float4*)&Bs[kk][tx * 8 + 4];
            float b[8] = {b0.x, b0.y, b0.z, b0.w, b1.x, b1.y, b1.z, b1.w};
#pragma unroll
            for (int i = 0; i < 4; i++)
#pragma unroll
                for (int j = 0; j < 8; j++) acc[i][j] += a[i] * b[j];
        }
        __syncthreads();
    }

    float bb[8];
#pragma unroll
    for (int j = 0; j < 8; j++) bb[j] = bias ? bias[jBase + tx * 8 + j] : 0.0f;
#pragma unroll
    for (int i = 0; i < 4; i++) {
        int m = mBase + ty * 4 + i;
        float4 o0, o1;
        o0.x = acc[i][0] + bb[0]; o0.y = acc[i][1] + bb[1];
        o0.z = acc[i][2] + bb[2]; o0.w = acc[i][3] + bb[3];
        o1.x = acc[i][4] + bb[4]; o1.y = acc[i][5] + bb[5];
        o1.z = acc[i][6] + bb[6]; o1.w = acc[i][7] + bb[7];
        *(float4*)(C + (size_t)m * Nout + jBase + tx * 8)     = o0;
        *(float4*)(C + (size_t)m * Nout + jBase + tx * 8 + 4) = o1;
    }
}

// ---------------- GCN aggregation + epilogue --------------------------------
// grid = NN blocks; 8 warps per block = 8 time steps; lane owns float4 of H=128.
__global__ void k_gcn_agg(const float* __restrict__ hw, const float* __restrict__ bias,
                          const float* __restrict__ bng, const float* __restrict__ bnb,
                          const float* __restrict__ bnm, const float* __restrict__ bnv,
                          int use_bn, float* __restrict__ out) {
    int n = blockIdx.x;
    int t = threadIdx.x >> 5;
    int lane = threadIdx.x & 31;
    int c0 = lane * 4;

    int p0 = g_rowptr[n], p1 = g_rowptr[n + 1];
    float4 acc = make_float4(0.f, 0.f, 0.f, 0.f);
    for (int p = p0; p < p1; p++) {
        int s = g_csr_src[p];
        float cf = g_csr_coef[p];
        float4 v = *(const float4*)(hw + ((size_t)t * NN + s) * HID + c0);
        acc.x += v.x * cf; acc.y += v.y * cf;
        acc.z += v.z * cf; acc.w += v.w * cf;
    }
    float d = g_dis[n];
    float sw = d * d;
    float4 hv = *(const float4*)(hw + ((size_t)t * NN + n) * HID + c0);
    float r[4];
    r[0] = acc.x + hv.x * sw + bias[c0 + 0];
    r[1] = acc.y + hv.y * sw + bias[c0 + 1];
    r[2] = acc.z + hv.z * sw + bias[c0 + 2];
    r[3] = acc.w + hv.w * sw + bias[c0 + 3];
#pragma unroll
    for (int q = 0; q < 4; q++) {
        float v = fmaxf(r[q], 0.0f);
        if (use_bn) {
            int c = c0 + q;
            float sc = bng[c] * rsqrtf(bnv[c] + EPSBN);
            v = (v - bnm[c]) * sc + bnb[c];
        }
        r[q] = v;
    }
    float4 o = make_float4(r[0], r[1], r[2], r[3]);
    *(float4*)(out + ((size_t)t * NN + n) * HID + c0) = o;
}

// ---------------- LSTM recurrence (one layer) -------------------------------
// pre: [T,N,256] (x@Wih^T + b_ih + b_hh precomputed). whh: [256,64] row-major.
// block: 256 threads = 8 warps; each warp owns 4 nodes. h in smem, c in regs.
// gate mapping: lane holds gates j = i*32 + lane (i=0..7) ->
//   units u=lane (+32): i-gate i=0/1, f=2/3, g=4/5, o=6/7 all in-lane.
#define LSTM_SMEM ((64*257 + 32*64) * 4)

__device__ __forceinline__ float sigmoidf_(float x) {
    return 1.0f / (1.0f + __expf(-x));
}

__global__ void k_lstm(const float* __restrict__ pre, const float* __restrict__ whh,
                       float* __restrict__ ys, float* __restrict__ outFinal) {
    extern __shared__ float sm[];
    float* ws = sm;               // [64][257] transposed whh, padded
    float* hs = sm + 64 * 257;    // [32][64]

    int tid  = threadIdx.x;
    int warp = tid >> 5, lane = tid & 31;
    int nodeBase = blockIdx.x * 32 + warp * 4;

    // load whh transposed: ws[k*257 + j] = whh[j*64 + k]
    for (int idx = tid; idx < G4 * OUTD; idx += 256) {
        int j = idx >> 6, k = idx & 63;
        ws[k * 257 + j] = whh[idx];
    }
    // init h = 0
#pragma unroll
    for (int q = 0; q < 4; q++) {
        hs[(warp * 4 + q) * 64 + lane]      = 0.0f;
        hs[(warp * 4 + q) * 64 + lane + 32] = 0.0f;
    }
    float c[4][2];
#pragma unroll
    for (int q = 0; q < 4; q++) { c[q][0] = 0.0f; c[q][1] = 0.0f; }
    __syncthreads();

    for (int t = 0; t < T_STEPS; t++) {
        float g[4][8];
#pragma unroll
        for (int q = 0; q < 4; q++) {
            int n = nodeBase + q;
            if (n < NN) {
                const float* pb = pre + ((size_t)t * NN + n) * G4;
#pragma unroll
                for (int i = 0; i < 8; i++) g[q][i] = pb[i * 32 + lane];
            } else {
#pragma unroll
                for (int i = 0; i < 8; i++) g[q][i] = 0.0f;
            }
        }
#pragma unroll 4
        for (int k = 0; k < 64; k++) {
            float w[8];
#pragma unroll
            for (int i = 0; i < 8; i++) w[i] = ws[k * 257 + i * 32 + lane];
#pragma unroll
            for (int q = 0; q < 4; q++) {
                float hk = hs[(warp * 4 + q) * 64 + k];
#pragma unroll
                for (int i = 0; i < 8; i++) g[q][i] += hk * w[i];
            }
        }
        __syncwarp();
#pragma unroll
        for (int q = 0; q < 4; q++) {
            int n = nodeBase + q;
#pragma unroll
            for (int h2 = 0; h2 < 2; h2++) {
                float ig = sigmoidf_(g[q][0 + h2]);
                float fg = sigmoidf_(g[q][2 + h2]);
                float gg = tanhf(g[q][4 + h2]);
                float og = sigmoidf_(g[q][6 + h2]);
                float cn = fg * c[q][h2] + ig * gg;
                c[q][h2] = cn;
                float hn = og * tanhf(cn);
                int u = lane + 32 * h2;
                hs[(warp * 4 + q) * 64 + u] = hn;
                if (n < NN) {
                    if (ys) ys[((size_t)t * NN + n) * OUTD + u] = hn;
                    if (outFinal && t == T_STEPS - 1) outFinal[(size_t)n * OUTD + u] = hn;
                }
            }
        }
        __syncwarp();
    }
}

// ---------------- host ----------------
extern "C" void kernel_launch(void* const* d_in, const int* in_sizes, int n_in,
                              void* d_out, int out_size) {
    const float* x   = (const float*)d_in[0];
    const int*   ei  = (const int*)d_in[1];
    const int*   src = ei;
    const int*   dst = ei + EE;
    const float* wg[3] = {(const float*)d_in[2], (const float*)d_in[4], (const float*)d_in[6]};
    const float* bg[3] = {(const float*)d_in[3], (const float*)d_in[5], (const float*)d_in[7]};
    const float* bnG[2] = {(const float*)d_in[8],  (const float*)d_in[12]};
    const float* bnB[2] = {(const float*)d_in[9],  (const float*)d_in[13]};
    const float* bnM[2] = {(const float*)d_in[10], (const float*)d_in[14]};
    const float* bnV[2] = {(const float*)d_in[11], (const float*)d_in[15]};
    const float* wih[3] = {(const float*)d_in[16], (const float*)d_in[20], (const float*)d_in[24]};
    const float* whh[3] = {(const float*)d_in[17], (const float*)d_in[21], (const float*)d_in[25]};
    const float* bih[3] = {(const float*)d_in[18], (const float*)d_in[22], (const float*)d_in[26]};
    const float* bhh[3] = {(const float*)d_in[19], (const float*)d_in[23], (const float*)d_in[27]};
    float* out = (float*)d_out;

    float *p_hw, *p_h, *p_pre, *p_ysA, *p_ysB, *p_w0t, *p_w1t, *p_w2t, *p_bias;
    cudaGetSymbolAddress((void**)&p_hw,  g_hw);
    cudaGetSymbolAddress((void**)&p_h,   g_h);
    cudaGetSymbolAddress((void**)&p_pre, g_pre);
    cudaGetSymbolAddress((void**)&p_ysA, g_ysA);
    cudaGetSymbolAddress((void**)&p_ysB, g_ysB);
    cudaGetSymbolAddress((void**)&p_w0t, g_wih0t);
    cudaGetSymbolAddress((void**)&p_w1t, g_wih1t);
    cudaGetSymbolAddress((void**)&p_w2t, g_wih2t);
    cudaGetSymbolAddress((void**)&p_bias, g_biasc);

    cudaFuncSetAttribute(k_lstm, cudaFuncAttributeMaxDynamicSharedMemorySize, LSTM_SMEM);

    // ---- graph/degree setup ----
    k_zero_cnt<<<(NN + 255) / 256, 256>>>();
    k_hist<<<(EE + 255) / 256, 256>>>(dst);
    k_dis<<<(NN + 255) / 256, 256>>>();
    k_scan<<<1, 1024>>>();
    k_copy_cursor<<<(NN + 255) / 256, 256>>>();
    k_fill<<<(EE + 255) / 256, 256>>>(src, dst);

    // ---- weight prep ----
    k_transpose<<<(G4 * HID + 255) / 256, 256>>>(wih[0], p_w0t, HID);
    k_transpose<<<(G4 * OUTD + 255) / 256, 256>>>(wih[1], p_w1t, OUTD);
    k_transpose<<<(G4 * OUTD + 255) / 256, 256>>>(wih[2], p_w2t, OUTD);
    k_bias_sum<<<1, 256>>>(bih[0], bhh[0], p_bias + 0 * G4);
    k_bias_sum<<<1, 256>>>(bih[1], bhh[1], p_bias + 1 * G4);
    k_bias_sum<<<1, 256>>>(bih[2], bhh[2], p_bias + 2 * G4);

    dim3 g1(MROWS / 64, 1), g2(MROWS / 64, 2);

    // ---- GCN 0 ----
    k_gemm<<<g1, 256>>>(x, wg[0], nullptr, p_hw, MROWS, FIN, HID);
    k_gcn_agg<<<NN, 256>>>(p_hw, bg[0], bnG[0], bnB[0], bnM[0], bnV[0], 1, p_h);
    // ---- GCN 1 ----
    k_gemm<<<g1, 256>>>(p_h, wg[1], nullptr, p_hw, MROWS, HID, HID);
    k_gcn_agg<<<NN, 256>>>(p_hw, bg[1], bnG[1], bnB[1], bnM[1], bnV[1], 1, p_h);
    // ---- GCN 2 ----
    k_gemm<<<g1, 256>>>(p_h, wg[2], nullptr, p_hw, MROWS, HID, HID);
    k_gcn_agg<<<NN, 256>>>(p_hw, bg[2], nullptr, nullptr, nullptr, nullptr, 0, p_h);

    int lstmBlocks = (NN + 31) / 32;
    // ---- LSTM layer 0 ----
    k_gemm<<<g2, 256>>>(p_h, p_w0t, p_bias + 0 * G4, p_pre, MROWS, HID, G4);
    k_lstm<<<lstmBlocks, 256, LSTM_SMEM>>>(p_pre, whh[0], p_ysA, nullptr);
    // ---- LSTM layer 1 ----
    k_gemm<<<g2, 256>>>(p_ysA, p_w1t, p_bias + 1 * G4, p_pre, MROWS, OUTD, G4);
    k_lstm<<<lstmBlocks, 256, LSTM_SMEM>>>(p_pre, whh[1], p_ysB, nullptr);
    // ---- LSTM layer 2 ----
    k_gemm<<<g2, 256>>>(p_ysB, p_w2t, p_bias + 2 * G4, p_pre, MROWS, OUTD, G4);
    k_lstm<<<lstmBlocks, 256, LSTM_SMEM>>>(p_pre, whh[2], nullptr, out);
}

// round 3
// speedup vs baseline: 1.3224x; 1.3224x over previous
#include <cuda_runtime.h>
#include <cuda_bf16.h>
#include <math.h>
#include <stdint.h>

#define T_STEPS 8
#define NN      10000
#define EE      200000
#define FIN     32
#define HID     128
#define OUTD    64
#define G4      256            // 4*OUT
#define MROWS   (T_STEPS*NN)   // 80000
#define EPSBN   1e-5f

// ===================== scratch (device globals) =====================
static __device__ float g_hw [MROWS*HID];   // agg output z (F=32 or 128)
static __device__ float g_h  [MROWS*HID];   // GCN layer output
static __device__ float g_pre[MROWS*G4];    // LSTM input projections
static __device__ float g_ysA[MROWS*OUTD];
static __device__ float g_ysB[MROWS*OUTD];
static __device__ float g_dis[NN];
static __device__ int   g_cnt[NN];
static __device__ int   g_rowptr[NN+1];
static __device__ int   g_cursor[NN];
static __device__ int   g_csr_src[EE];
static __device__ float g_csr_coef[EE];
static __device__ float g_biasc[3*G4];      // b_ih + b_hh per layer

// ===================== helpers =====================
__device__ __forceinline__ uint32_t smem_u32(const void* p) {
    uint32_t a;
    asm("{ .reg .u64 t; cvta.to.shared.u64 t, %1; cvt.u32.u64 %0, t; }" : "=r"(a) : "l"(p));
    return a;
}
__device__ __forceinline__ void ldsm_x4(uint32_t* r, uint32_t addr) {
    asm volatile("ldmatrix.sync.aligned.m8n8.x4.shared.b16 {%0,%1,%2,%3}, [%4];"
                 : "=r"(r[0]), "=r"(r[1]), "=r"(r[2]), "=r"(r[3]) : "r"(addr));
}
__device__ __forceinline__ void mma16816(float* d, const uint32_t* a, const uint32_t* b) {
    asm volatile(
        "mma.sync.aligned.m16n8k16.row.col.f32.bf16.bf16.f32 "
        "{%0,%1,%2,%3}, {%4,%5,%6,%7}, {%8,%9}, {%0,%1,%2,%3};"
        : "+f"(d[0]), "+f"(d[1]), "+f"(d[2]), "+f"(d[3])
        : "r"(a[0]), "r"(a[1]), "r"(a[2]), "r"(a[3]), "r"(b[0]), "r"(b[1]));
}
__device__ __forceinline__ uint32_t pack_hi2(float x, float y) {
    __nv_bfloat162 h = __halves2bfloat162(__float2bfloat16(x), __float2bfloat16(y));
    return *(uint32_t*)&h;
}
__device__ __forceinline__ uint32_t pack_lo2(float x, float y) {
    float hx = __bfloat162float(__float2bfloat16(x));
    float hy = __bfloat162float(__float2bfloat16(y));
    __nv_bfloat162 l = __halves2bfloat162(__float2bfloat16(x - hx), __float2bfloat16(y - hy));
    return *(uint32_t*)&l;
}

// ===================== graph setup =====================
__global__ void k_zero_cnt() {
    int i = blockIdx.x * blockDim.x + threadIdx.x;
    if (i < NN) g_cnt[i] = 0;
}
__global__ void k_hist(const int* __restrict__ dst) {
    int e = blockIdx.x * blockDim.x + threadIdx.x;
    if (e < EE) atomicAdd(&g_cnt[dst[e]], 1);
}
__global__ void k_dis() {
    int i = blockIdx.x * blockDim.x + threadIdx.x;
    if (i < NN) g_dis[i] = rsqrtf((float)g_cnt[i] + 1.0f);
}
__global__ void k_scan() {
    const int TPB = 1024, PER = 10;
    __shared__ int sh[TPB];
    int tid = threadIdx.x;
    int base = tid * PER;
    int loc[PER];
    int s = 0;
#pragma unroll
    for (int i = 0; i < PER; i++) {
        int idx = base + i;
        int v = (idx < NN) ? g_cnt[idx] : 0;
        loc[i] = s; s += v;
    }
    sh[tid] = s; __syncthreads();
    for (int off = 1; off < TPB; off <<= 1) {
        int v = (tid >= off) ? sh[tid - off] : 0;
        __syncthreads();
        sh[tid] += v;
        __syncthreads();
    }
    int excl = (tid == 0) ? 0 : sh[tid - 1];
#pragma unroll
    for (int i = 0; i < PER; i++) {
        int idx = base + i;
        if (idx <= NN) g_rowptr[idx] = excl + loc[i];
    }
}
__global__ void k_copy_cursor() {
    int i = blockIdx.x * blockDim.x + threadIdx.x;
    if (i < NN) g_cursor[i] = g_rowptr[i];
}
__global__ void k_fill(const int* __restrict__ src, const int* __restrict__ dst) {
    int e = blockIdx.x * blockDim.x + threadIdx.x;
    if (e < EE) {
        int s = src[e], d = dst[e];
        int p = atomicAdd(&g_cursor[d], 1);
        g_csr_src[p]  = s;
        g_csr_coef[p] = g_dis[s] * g_dis[d];
    }
}
__global__ void k_bias_sum(const float* __restrict__ a, const float* __restrict__ b,
                           float* __restrict__ o) {
    int i = threadIdx.x;
    o[i] = a[i] + b[i];
}

// ===================== GCN aggregation: z = Â h (incl. self loop) ============
template <int F>
__global__ void k_agg(const float* __restrict__ in, float* __restrict__ out) {
    int n = blockIdx.x;
    int t = threadIdx.x >> 5;
    int lane = threadIdx.x & 31;
    int p0 = g_rowptr[n], p1 = g_rowptr[n + 1];
    float d = g_dis[n];
    float sw = d * d;
    if (F == 128) {
        int c0 = lane * 4;
        float4 acc = make_float4(0.f, 0.f, 0.f, 0.f);
        for (int p = p0; p < p1; p++) {
            int s = g_csr_src[p];
            float cf = g_csr_coef[p];
            float4 v = *(const float4*)(in + ((size_t)t * NN + s) * F + c0);
            acc.x += v.x * cf; acc.y += v.y * cf;
            acc.z += v.z * cf; acc.w += v.w * cf;
        }
        float4 hv = *(const float4*)(in + ((size_t)t * NN + n) * F + c0);
        float4 o;
        o.x = acc.x + hv.x * sw; o.y = acc.y + hv.y * sw;
        o.z = acc.z + hv.z * sw; o.w = acc.w + hv.w * sw;
        *(float4*)(out + ((size_t)t * NN + n) * F + c0) = o;
    } else {  // F == 32
        float acc = 0.0f;
        for (int p = p0; p < p1; p++) {
            int s = g_csr_src[p];
            acc += in[((size_t)t * NN + s) * F + lane] * g_csr_coef[p];
        }
        out[((size_t)t * NN + n) * F + lane] =
            acc + in[((size_t)t * NN + n) * F + lane] * sw;
    }
}

// ===================== mma.sync bf16x3 GEMM =================================
// C[M,Nout] = A[M,K] @ W (+ epilogue). CTA tile 128x128, 256 threads (8 warps,
// 2(M) x 4(N)), warp tile 64x32. Whole K staged in smem as bf16 hi/lo.
// WNK=0: W[K,Nout] (GCN weights, transpose-on-load). WNK=1: W[Nout,K] (LSTM).
// mode: 0 = +bias ; 1 = relu(.+bias) ; 2 = bn(relu(.+bias))
template <int K, int WNK>
__global__ void __launch_bounds__(256)
k_gemm_mma(const float* __restrict__ A, const float* __restrict__ W,
           const float* __restrict__ bias,
           const float* __restrict__ bng, const float* __restrict__ bnb,
           const float* __restrict__ bnm, const float* __restrict__ bnv,
           int mode, int Nout, float* __restrict__ C) {
    constexpr int P  = K + 8;       // bf16 pitch: row stride ≡ 4 mod 8 word-groups
    constexpr int P2 = P * 2;       // bytes
    constexpr int S  = 128 * P2;    // one 128-row tile
    extern __shared__ char sm[];
    char* Ahi = sm;
    char* Alo = sm + S;
    char* Bhi = sm + 2 * S;
    char* Blo = sm + 3 * S;

    int tid = threadIdx.x, wid = tid >> 5, lane = tid & 31;
    int wm = wid & 1, wn = wid >> 1;
    int mBase = blockIdx.x * 128;
    int jBase = blockIdx.y * 128;

    // ---- stage A (128 x K) as hi/lo bf16 ----
    {
        constexpr int KQ = K / 4;
        for (int idx = tid; idx < 128 * KQ; idx += 256) {
            int row = idx / KQ;
            int kq  = (idx % KQ) * 4;
            float4 v = *(const float4*)(A + (size_t)(mBase + row) * K + kq);
            uint32_t* ph = (uint32_t*)(Ahi + row * P2 + kq * 2);
            uint32_t* pl = (uint32_t*)(Alo + row * P2 + kq * 2);
            ph[0] = pack_hi2(v.x, v.y); ph[1] = pack_hi2(v.z, v.w);
            pl[0] = pack_lo2(v.x, v.y); pl[1] = pack_lo2(v.z, v.w);
        }
    }
    // ---- stage B (128 n-rows x K) as hi/lo bf16, layout [n][k] ----
    if (WNK) {
        constexpr int KQ = K / 4;
        for (int idx = tid; idx < 128 * KQ; idx += 256) {
            int n  = idx / KQ;
            int kq = (idx % KQ) * 4;
            float4 v = *(const float4*)(W + (size_t)(jBase + n) * K + kq);
            uint32_t* ph = (uint32_t*)(Bhi + n * P2 + kq * 2);
            uint32_t* pl = (uint32_t*)(Blo + n * P2 + kq * 2);
            ph[0] = pack_hi2(v.x, v.y); ph[1] = pack_hi2(v.z, v.w);
            pl[0] = pack_lo2(v.x, v.y); pl[1] = pack_lo2(v.z, v.w);
        }
    } else {
        for (int idx = tid; idx < K * 128; idx += 256) {
            int k = idx >> 7, n = idx & 127;
            float v = W[(size_t)k * Nout + jBase + n];
            float hv = __bfloat162float(__float2bfloat16(v));
            *(__nv_bfloat16*)(Bhi + n * P2 + k * 2) = __float2bfloat16(v);
            *(__nv_bfloat16*)(Blo + n * P2 + k * 2) = __float2bfloat16(v - hv);
        }
    }
    __syncthreads();

    // ---- mainloop ----
    float acc[4][4][4];
#pragma unroll
    for (int i = 0; i < 4; i++)
#pragma unroll
        for (int j = 0; j < 4; j++)
#pragma unroll
            for (int r = 0; r < 4; r++) acc[i][j][r] = 0.0f;

    uint32_t aOff = (uint32_t)((wm * 64 + (lane & 15)) * P2 + (lane >> 4) * 16);
    uint32_t bOff = (uint32_t)((wn * 32 + (lane & 7) + ((lane >> 4) << 3)) * P2 +
                               ((lane >> 3) & 1) * 16);
    uint32_t aHiB = smem_u32(Ahi) + aOff;
    uint32_t aLoB = smem_u32(Alo) + aOff;
    uint32_t bHiB = smem_u32(Bhi) + bOff;
    uint32_t bLoB = smem_u32(Blo) + bOff;

#pragma unroll
    for (int ks = 0; ks < K / 16; ks++) {
        uint32_t ka = ks * 32;
        uint32_t ah[4][4], al[4][4], bh[2][4], bl[2][4];
#pragma unroll
        for (int i = 0; i < 4; i++) {
            ldsm_x4(ah[i], aHiB + i * (16 * P2) + ka);
            ldsm_x4(al[i], aLoB + i * (16 * P2) + ka);
        }
#pragma unroll
        for (int j2 = 0; j2 < 2; j2++) {
            ldsm_x4(bh[j2], bHiB + j2 * (16 * P2) + ka);
            ldsm_x4(bl[j2], bLoB + j2 * (16 * P2) + ka);
        }
#pragma unroll
        for (int i = 0; i < 4; i++)
#pragma unroll
            for (int j = 0; j < 4; j++)
                mma16816(acc[i][j], ah[i], &bh[j >> 1][(j & 1) * 2]);
#pragma unroll
        for (int i = 0; i < 4; i++)
#pragma unroll
            for (int j = 0; j < 4; j++)
                mma16816(acc[i][j], ah[i], &bl[j >> 1][(j & 1) * 2]);
#pragma unroll
        for (int i = 0; i < 4; i++)
#pragma unroll
            for (int j = 0; j < 4; j++)
                mma16816(acc[i][j], al[i], &bh[j >> 1][(j & 1) * 2]);
    }

    // ---- epilogue ----
    float pb[4][2], psc[4][2], pmn[4][2], pbb[4][2];
#pragma unroll
    for (int j = 0; j < 4; j++) {
        int c = jBase + wn * 32 + j * 8 + (lane & 3) * 2;
#pragma unroll
        for (int q = 0; q < 2; q++) {
            pb[j][q] = bias ? bias[c + q] : 0.0f;
            if (mode == 2) {
                psc[j][q] = bng[c + q] * rsqrtf(bnv[c + q] + EPSBN);
                pmn[j][q] = bnm[c + q];
                pbb[j][q] = bnb[c + q];
            }
        }
    }
#pragma unroll
    for (int i = 0; i < 4; i++) {
        int r0 = mBase + wm * 64 + i * 16 + (lane >> 2);
#pragma unroll
        for (int j = 0; j < 4; j++) {
            int c = jBase + wn * 32 + j * 8 + (lane & 3) * 2;
            float v[4];
#pragma unroll
            for (int r = 0; r < 4; r++) {
                float x = acc[i][j][r] + pb[j][r & 1];
                if (mode >= 1) x = fmaxf(x, 0.0f);
                if (mode == 2) x = (x - pmn[j][r & 1]) * psc[j][r & 1] + pbb[j][r & 1];
                v[r] = x;
            }
            *(float2*)(C + (size_t)r0 * Nout + c)       = make_float2(v[0], v[1]);
            *(float2*)(C + (size_t)(r0 + 8) * Nout + c) = make_float2(v[2], v[3]);
        }
    }
}

// ===================== LSTM recurrence ======================================
#define LSTM_SMEM ((64*257 + 32*64) * 4)

__device__ __forceinline__ float sigmoidf_(float x) {
    return 1.0f / (1.0f + __expf(-x));
}

__global__ void k_lstm(const float* __restrict__ pre, const float* __restrict__ whh,
                       float* __restrict__ ys, float* __restrict__ outFinal) {
    extern __shared__ float smf[];
    float* ws = smf;               // [64][257] transposed whh, padded
    float* hs = smf + 64 * 257;    // [32][64]

    int tid  = threadIdx.x;
    int warp = tid >> 5, lane = tid & 31;
    int nodeBase = blockIdx.x * 32 + warp * 4;

    for (int idx = tid; idx < G4 * OUTD; idx += 256) {
        int j = idx >> 6, k = idx & 63;
        ws[k * 257 + j] = whh[idx];
    }
#pragma unroll
    for (int q = 0; q < 4; q++) {
        hs[(warp * 4 + q) * 64 + lane]      = 0.0f;
        hs[(warp * 4 + q) * 64 + lane + 32] = 0.0f;
    }
    float c[4][2];
#pragma unroll
    for (int q = 0; q < 4; q++) { c[q][0] = 0.0f; c[q][1] = 0.0f; }
    __syncthreads();

    for (int t = 0; t < T_STEPS; t++) {
        float g[4][8];
#pragma unroll
        for (int q = 0; q < 4; q++) {
            int n = nodeBase + q;
            if (n < NN) {
                const float* pb = pre + ((size_t)t * NN + n) * G4;
#pragma unroll
                for (int i = 0; i < 8; i++) g[q][i] = pb[i * 32 + lane];
            } else {
#pragma unroll
                for (int i = 0; i < 8; i++) g[q][i] = 0.0f;
            }
        }
#pragma unroll 4
        for (int k = 0; k < 64; k++) {
            float w[8];
#pragma unroll
            for (int i = 0; i < 8; i++) w[i] = ws[k * 257 + i * 32 + lane];
#pragma unroll
            for (int q = 0; q < 4; q++) {
                float hk = hs[(warp * 4 + q) * 64 + k];
#pragma unroll
                for (int i = 0; i < 8; i++) g[q][i] += hk * w[i];
            }
        }
        __syncwarp();
#pragma unroll
        for (int q = 0; q < 4; q++) {
            int n = nodeBase + q;
#pragma unroll
            for (int h2 = 0; h2 < 2; h2++) {
                float ig = sigmoidf_(g[q][0 + h2]);
                float fg = sigmoidf_(g[q][2 + h2]);
                float gg = tanhf(g[q][4 + h2]);
                float og = sigmoidf_(g[q][6 + h2]);
                float cn = fg * c[q][h2] + ig * gg;
                c[q][h2] = cn;
                float hn = og * tanhf(cn);
                int u = lane + 32 * h2;
                hs[(warp * 4 + q) * 64 + u] = hn;
                if (n < NN) {
                    if (ys) ys[((size_t)t * NN + n) * OUTD + u] = hn;
                    if (outFinal && t == T_STEPS - 1) outFinal[(size_t)n * OUTD + u] = hn;
                }
            }
        }
        __syncwarp();
    }
}

// ===================== host =====================
extern "C" void kernel_launch(void* const* d_in, const int* in_sizes, int n_in,
                              void* d_out, int out_size) {
    const float* x   = (const float*)d_in[0];
    const int*   ei  = (const int*)d_in[1];
    const int*   src = ei;
    const int*   dst = ei + EE;
    const float* wg[3] = {(const float*)d_in[2], (const float*)d_in[4], (const float*)d_in[6]};
    const float* bg[3] = {(const float*)d_in[3], (const float*)d_in[5], (const float*)d_in[7]};
    const float* bnG[2] = {(const float*)d_in[8],  (const float*)d_in[12]};
    const float* bnB[2] = {(const float*)d_in[9],  (const float*)d_in[13]};
    const float* bnM[2] = {(const float*)d_in[10], (const float*)d_in[14]};
    const float* bnV[2] = {(const float*)d_in[11], (const float*)d_in[15]};
    const float* wih[3] = {(const float*)d_in[16], (const float*)d_in[20], (const float*)d_in[24]};
    const float* whh[3] = {(const float*)d_in[17], (const float*)d_in[21], (const float*)d_in[25]};
    const float* bih[3] = {(const float*)d_in[18], (const float*)d_in[22], (const float*)d_in[26]};
    const float* bhh[3] = {(const float*)d_in[19], (const float*)d_in[23], (const float*)d_in[27]};
    float* out = (float*)d_out;

    float *p_hw, *p_h, *p_pre, *p_ysA, *p_ysB, *p_bias;
    cudaGetSymbolAddress((void**)&p_hw,  g_hw);
    cudaGetSymbolAddress((void**)&p_h,   g_h);
    cudaGetSymbolAddress((void**)&p_pre, g_pre);
    cudaGetSymbolAddress((void**)&p_ysA, g_ysA);
    cudaGetSymbolAddress((void**)&p_ysB, g_ysB);
    cudaGetSymbolAddress((void**)&p_bias, g_biasc);

    cudaFuncSetAttribute(k_lstm, cudaFuncAttributeMaxDynamicSharedMemorySize, LSTM_SMEM);
    // dyn smem = 4 tiles * 128 * (K+8) * 2 bytes
    const int SM32  = 4 * 128 * (32  + 8) * 2;   //  40960
    const int SM64  = 4 * 128 * (64  + 8) * 2;   //  73728
    const int SM128 = 4 * 128 * (128 + 8) * 2;   // 139264
    cudaFuncSetAttribute(k_gemm_mma<32, 0>,  cudaFuncAttributeMaxDynamicSharedMemorySize, SM32);
    cudaFuncSetAttribute(k_gemm_mma<128, 0>, cudaFuncAttributeMaxDynamicSharedMemorySize, SM128);
    cudaFuncSetAttribute(k_gemm_mma<128, 1>, cudaFuncAttributeMaxDynamicSharedMemorySize, SM128);
    cudaFuncSetAttribute(k_gemm_mma<64, 1>,  cudaFuncAttributeMaxDynamicSharedMemorySize, SM64);

    // ---- graph/degree setup ----
    k_zero_cnt<<<(NN + 255) / 256, 256>>>();
    k_hist<<<(EE + 255) / 256, 256>>>(dst);
    k_dis<<<(NN + 255) / 256, 256>>>();
    k_scan<<<1, 1024>>>();
    k_copy_cursor<<<(NN + 255) / 256, 256>>>();
    k_fill<<<(EE + 255) / 256, 256>>>(src, dst);

    k_bias_sum<<<1, 256>>>(bih[0], bhh[0], p_bias + 0 * G4);
    k_bias_sum<<<1, 256>>>(bih[1], bhh[1], p_bias + 1 * G4);
    k_bias_sum<<<1, 256>>>(bih[2], bhh[2], p_bias + 2 * G4);

    const int MT = MROWS / 128;  // 625 M tiles

    // ---- GCN 0: z = Agg(x) [F=32]; h = bn(relu(z@W0 + b0)) ----
    k_agg<32><<<NN, 256>>>(x, p_hw);
    k_gemm_mma<32, 0><<<dim3(MT, 1), 256, SM32>>>(
        p_hw, wg[0], bg[0], bnG[0], bnB[0], bnM[0], bnV[0], 2, HID, p_h);
    // ---- GCN 1 ----
    k_agg<128><<<NN, 256>>>(p_h, p_hw);
    k_gemm_mma<128, 0><<<dim3(MT, 1), 256, SM128>>>(
        p_hw, wg[1], bg[1], bnG[1], bnB[1], bnM[1], bnV[1], 2, HID, p_h);
    // ---- GCN 2 (relu only) ----
    k_agg<128><<<NN, 256>>>(p_h, p_hw);
    k_gemm_mma<128, 0><<<dim3(MT, 1), 256, SM128>>>(
        p_hw, wg[2], bg[2], nullptr, nullptr, nullptr, nullptr, 1, HID, p_h);

    int lstmBlocks = (NN + 31) / 32;
    // ---- LSTM layer 0 ----
    k_gemm_mma<128, 1><<<dim3(MT, 2), 256, SM128>>>(
        p_h, wih[0], p_bias + 0 * G4, nullptr, nullptr, nullptr, nullptr, 0, G4, p_pre);
    k_lstm<<<lstmBlocks, 256, LSTM_SMEM>>>(p_pre, whh[0], p_ysA, nullptr);
    // ---- LSTM layer 1 ----
    k_gemm_mma<64, 1><<<dim3(MT, 2), 256, SM64>>>(
        p_ysA, wih[1], p_bias + 1 * G4, nullptr, nullptr, nullptr, nullptr, 0, G4, p_pre);
    k_lstm<<<lstmBlocks, 256, LSTM_SMEM>>>(p_pre, whh[1], p_ysB, nullptr);
    // ---- LSTM layer 2 ----
    k_gemm_mma<64, 1><<<dim3(MT, 2), 256, SM64>>>(
        p_ysB, wih[2], p_bias + 2 * G4, nullptr, nullptr, nullptr, nullptr, 0, G4, p_pre);
    k_lstm<<<lstmBlocks, 256, LSTM_SMEM>>>(p_pre, whh[2], nullptr, out);
}